// round 1
// baseline (speedup 1.0000x reference)
#include <cuda_runtime.h>

// LieTransport: out[b,c,y,x,r] = bilinear_border_sample(h_prev[b,c,:,:,r], grid(b,y,x))
// grid = base_grid - flow*dt, align_corners=False, padding=border.
// Shapes: h_prev [4,16,128,128,64] f32, flow [4,2,128,128] f32, dt [4] f32.
// Memory-bound: ~512 MB total traffic; one thread per output float4 (R chunk of 4).

#define B 4
#define C 16
#define H 128
#define W 128
#define R 64
#define R4 (R / 4)  // 16 float4 per row

__device__ __forceinline__ float4 f4_fma(float4 a, float s, float4 acc) {
    acc.x = fmaf(a.x, s, acc.x);
    acc.y = fmaf(a.y, s, acc.y);
    acc.z = fmaf(a.z, s, acc.z);
    acc.w = fmaf(a.w, s, acc.w);
    return acc;
}

__global__ void __launch_bounds__(256)
lie_transport_kernel(const float4* __restrict__ h4,
                     const float* __restrict__ flow,
                     const float* __restrict__ dt,
                     float4* __restrict__ out4)
{
    // idx layout (fastest -> slowest): r4 (16), x (128), y (128), c (16), b (4)
    int idx = blockIdx.x * blockDim.x + threadIdx.x;   // 0 .. 2^24-1
    int r4 = idx & (R4 - 1);
    int x  = (idx >> 4) & (W - 1);
    int y  = (idx >> 11) & (H - 1);
    int c  = (idx >> 18) & (C - 1);
    int b  = idx >> 22;

    // ---- sampling coordinates (depend on b,y,x only) ----
    float d   = __ldg(&dt[b]);
    float fdx = __ldg(&flow[((b * 2 + 0) * H + y) * W + x]);
    float fdy = __ldg(&flow[((b * 2 + 1) * H + y) * W + x]);

    // base grid (linspace -1..1), minus flow*dt
    float gx = fmaf((float)x, 2.0f / (W - 1), -1.0f) - fdx * d;
    float gy = fmaf((float)y, 2.0f / (H - 1), -1.0f) - fdy * d;

    // unnormalize (align_corners=False) + border clip
    float xs = fminf(fmaxf(((gx + 1.0f) * (float)W - 1.0f) * 0.5f, 0.0f), (float)(W - 1));
    float ys = fminf(fmaxf(((gy + 1.0f) * (float)H - 1.0f) * 0.5f, 0.0f), (float)(H - 1));

    float x0f = floorf(xs);
    float y0f = floorf(ys);
    float wx = xs - x0f;
    float wy = ys - y0f;

    int x0 = (int)x0f;
    int y0 = (int)y0f;
    int x1 = min(x0 + 1, W - 1);
    int y1 = min(y0 + 1, H - 1);

    // ---- gather 4 corner float4s and blend ----
    // float4 index: ((b*C + c)*H*W + y*W + x)*R4 + r4
    int bc = (b * C + c) * (H * W);
    const float4* rowbase = h4 + (size_t)r4;
    float4 v00 = __ldg(rowbase + (size_t)(bc + y0 * W + x0) * R4);
    float4 v01 = __ldg(rowbase + (size_t)(bc + y0 * W + x1) * R4);
    float4 v10 = __ldg(rowbase + (size_t)(bc + y1 * W + x0) * R4);
    float4 v11 = __ldg(rowbase + (size_t)(bc + y1 * W + x1) * R4);

    float w00 = (1.0f - wx) * (1.0f - wy);
    float w01 = wx * (1.0f - wy);
    float w10 = (1.0f - wx) * wy;
    float w11 = wx * wy;

    float4 acc;
    acc.x = v00.x * w00; acc.y = v00.y * w00; acc.z = v00.z * w00; acc.w = v00.w * w00;
    acc = f4_fma(v01, w01, acc);
    acc = f4_fma(v10, w10, acc);
    acc = f4_fma(v11, w11, acc);

    out4[idx] = acc;
}

extern "C" void kernel_launch(void* const* d_in, const int* in_sizes, int n_in,
                              void* d_out, int out_size)
{
    // Resolve inputs by element count (robust to ordering):
    //   h_prev: 4*16*128*128*64 = 67108864, flow: 4*2*128*128 = 131072, dt: 4
    const float* h_prev = nullptr;
    const float* flow   = nullptr;
    const float* dt     = nullptr;
    for (int i = 0; i < n_in; ++i) {
        if (in_sizes[i] == B * C * H * W * R)      h_prev = (const float*)d_in[i];
        else if (in_sizes[i] == B * 2 * H * W)     flow   = (const float*)d_in[i];
        else if (in_sizes[i] == B)                 dt     = (const float*)d_in[i];
    }

    int total4 = B * C * H * W * R4;               // 16,777,216 threads
    int threads = 256;
    int blocks = total4 / threads;                 // 65,536

    lie_transport_kernel<<<blocks, threads>>>(
        (const float4*)h_prev, flow, dt, (float4*)d_out);
}